// round 7
// baseline (speedup 1.0000x reference)
#include <cuda_runtime.h>
#include <cuda_bf16.h>
#include <cstdint>

static constexpr int NG      = 2500;
static constexpr int NT      = 20000;
static constexpr int NE      = 640000;
static constexpr int SRC_DIM = 128;
static constexpr int DST_DIM = 500;
static constexpr int HID     = 128;
static constexpr int OUTD    = 128;
static constexpr int NCLS    = 16;

// ---------------- scratch (device globals: no allocation allowed) ----------------
__device__ float g_agg[NT * SRC_DIM];
__device__ int   g_deg[NT];          // zero-init at load; re-zeroed by k_scan each run
__device__ int   g_rowptr[NT + 1];
__device__ int   g_cursor[NT];
__device__ int   g_colidx[NE];
// weights as bf16 hi/lo planes: [w(6)][plane(2)][n(128)][k(512 padded)]
__device__ __nv_bfloat16 g_wtb[6 * 2 * 128 * 512];

static constexpr size_t WST = (size_t)2 * 128 * 512;   // slot stride in elements

// ---------------- k_trh: weight transpose + bf16 split + edge histogram ----------------
__global__ void k_trh(const float* __restrict__ W1s, const float* __restrict__ W1n,
                      const float* __restrict__ W2s, const float* __restrict__ W2n,
                      const float* __restrict__ Wc1, const float* __restrict__ Wc2,
                      const int* __restrict__ edst) {
    int t = blockIdx.x * blockDim.x + threadIdx.x;
    // histogram: 2 edges per thread (g_deg is zero on entry: static init / k_scan re-zero)
    int e0 = t * 2;
    if (e0 < NE)     atomicAdd(&g_deg[__ldg(&edst[e0])], 1);
    if (e0 + 1 < NE) atomicAdd(&g_deg[__ldg(&edst[e0 + 1])], 1);

    if (t >= 6 * 65536) return;
    int w   = t >> 16;
    int rem = t & 65535;
    int n   = rem >> 9;
    int k   = rem & 511;
    float v = 0.f;
    if (w == 0)      { if (k < DST_DIM) v = W1s[(size_t)k * 128 + n]; }
    else if (w == 1) { if (k < 128)     v = W1n[(size_t)k * 128 + n]; }
    else if (w == 2) { if (k < 128)     v = W2s[(size_t)k * 128 + n]; }
    else if (w == 3) { if (k < 128)     v = W2n[(size_t)k * 128 + n]; }
    else if (w == 4) { if (k < 128)     v = Wc1[(size_t)k * 128 + n]; }
    else             { if (k < 128 && n < NCLS) v = Wc2[(size_t)k * NCLS + n]; }
    __nv_bfloat16 hb = __float2bfloat16_rn(v);
    float lo = v - __bfloat162float(hb);
    g_wtb[(size_t)w * WST + (size_t)n * 512 + k] = hb;
    g_wtb[(size_t)w * WST + 128 * 512 + (size_t)n * 512 + k] = __float2bfloat16_rn(lo);
}

// ---------------- single-pass scan (also re-zeros g_deg for the next replay) ----------------
__global__ void __launch_bounds__(1024) k_scan() {
    constexpr int PER = 20;
    __shared__ int wsum[32];
    const int tid  = threadIdx.x;
    const int lane = tid & 31;
    const int wid  = tid >> 5;
    const int base = tid * PER;

    int pref[PER];
    int s = 0;
    #pragma unroll
    for (int q = 0; q < PER; ++q) {
        int i = base + q;
        int d = 0;
        if (i < NT) { d = g_deg[i]; g_deg[i] = 0; }
        pref[q] = s;
        s += d;
    }
    int x = s;
    #pragma unroll
    for (int off = 1; off < 32; off <<= 1) {
        int y = __shfl_up_sync(0xffffffffu, x, off);
        if (lane >= off) x += y;
    }
    if (lane == 31) wsum[wid] = x;
    __syncthreads();
    if (wid == 0) {
        int w = wsum[lane];
        #pragma unroll
        for (int off = 1; off < 32; off <<= 1) {
            int y = __shfl_up_sync(0xffffffffu, w, off);
            if (lane >= off) w += y;
        }
        wsum[lane] = w;
    }
    __syncthreads();
    const int tbase = (x - s) + (wid ? wsum[wid - 1] : 0);
    #pragma unroll
    for (int q = 0; q < PER; ++q) {
        int i = base + q;
        if (i < NT) {
            int rp = tbase + pref[q];
            g_rowptr[i] = rp;
            g_cursor[i] = rp;
        }
    }
    if (tid == 1023) g_rowptr[NT] = tbase + s;
}

__global__ void k_scatter(const int* __restrict__ src, const int* __restrict__ dst) {
    int e0 = (blockIdx.x * blockDim.x + threadIdx.x) * 2;
    #pragma unroll
    for (int q = 0; q < 2; ++q) {
        int e = e0 + q;
        if (e < NE) {
            int p = atomicAdd(&g_cursor[__ldg(&dst[e])], 1);
            g_colidx[p] = __ldg(&src[e]);
        }
    }
}

// ---------------- SpMM mean: one warp per dst row ----------------
__global__ void __launch_bounds__(256) k_spmm(const float* __restrict__ gene) {
    int row  = (blockIdx.x * blockDim.x + threadIdx.x) >> 5;
    int lane = threadIdx.x & 31;
    if (row >= NT) return;
    int beg = g_rowptr[row];
    int end = g_rowptr[row + 1];
    float4 a = make_float4(0.f, 0.f, 0.f, 0.f);
    for (int base = beg; base < end; base += 32) {
        int myidx = (base + lane < end) ? g_colidx[base + lane] : 0;
        int cnt = min(32, end - base);
        int j = 0;
        for (; j + 4 <= cnt; j += 4) {
            int s0 = __shfl_sync(0xffffffffu, myidx, j);
            int s1 = __shfl_sync(0xffffffffu, myidx, j + 1);
            int s2 = __shfl_sync(0xffffffffu, myidx, j + 2);
            int s3 = __shfl_sync(0xffffffffu, myidx, j + 3);
            float4 v0 = *((const float4*)(gene + (size_t)s0 * SRC_DIM) + lane);
            float4 v1 = *((const float4*)(gene + (size_t)s1 * SRC_DIM) + lane);
            float4 v2 = *((const float4*)(gene + (size_t)s2 * SRC_DIM) + lane);
            float4 v3 = *((const float4*)(gene + (size_t)s3 * SRC_DIM) + lane);
            a.x += v0.x + v1.x + v2.x + v3.x;
            a.y += v0.y + v1.y + v2.y + v3.y;
            a.z += v0.z + v1.z + v2.z + v3.z;
            a.w += v0.w + v1.w + v2.w + v3.w;
        }
        for (; j < cnt; ++j) {
            int s = __shfl_sync(0xffffffffu, myidx, j);
            float4 v = *((const float4*)(gene + (size_t)s * SRC_DIM) + lane);
            a.x += v.x; a.y += v.y; a.z += v.z; a.w += v.w;
        }
    }
    float inv = 1.0f / (float)max(end - beg, 1);
    a.x *= inv; a.y *= inv; a.z *= inv; a.w *= inv;
    *((float4*)(g_agg + (size_t)row * SRC_DIM) + lane) = a;
}

// ---------------- fused 4-layer network kernel ----------------
// Per CTA (128 rows): L0 h1 = relu(train@W1s + agg@W1n + b1)
//                     L1 h2 = relu(h1@W2s + agg@W2n + b2)
//                     L2 h3 = relu(h2@Wc1 + bc1)
//                     L3 out = h3@Wc2 + bc2   (N=16)
// h1/h2/h3 live in smem as bf16 hi/lo A-tiles; B streams via cp.async.
static constexpr int SP      = 40;                 // bf16 tile pitch (80B, conflict-free)
static constexpr int PLANE_B = 128 * SP * 2;       // 10240 B per (chunk,plane) tile
static constexpr int OFF_H   = 0;                  // H[ch(4)][plane(2)]
static constexpr int OFF_AST = 8 * PLANE_B;        // Astage[s(2)][plane(2)]
static constexpr int OFF_BS  = OFF_AST + 4 * PLANE_B;  // Bs[s(2)][plane(2)]
static constexpr int OFF_AFP = OFF_BS + 4 * PLANE_B;   // fp32 staging 128 x 36 floats
static constexpr int SMEM_FUSED = OFF_AFP + 128 * 144; // 182272

__device__ __forceinline__ uint32_t smem_u32(const void* p) {
    uint32_t a;
    asm("{ .reg .u64 t; cvta.to.shared.u64 t, %1; cvt.u32.u64 %0, t; }" : "=r"(a) : "l"(p));
    return a;
}
#define CP16(dst, src) \
    asm volatile("cp.async.ca.shared.global [%0], [%1], 16;" :: "r"(dst), "l"(src))
#define CP16Z(dst, src, nb) \
    asm volatile("cp.async.ca.shared.global [%0], [%1], 16, %2;" :: "r"(dst), "l"(src), "r"(nb))
#define CP_COMMIT() asm volatile("cp.async.commit_group;" ::: "memory")
#define CP_WAIT1()  asm volatile("cp.async.wait_group 1;" ::: "memory")
#define CP_WAIT0()  asm volatile("cp.async.wait_group 0;" ::: "memory")

__device__ __forceinline__ void mma16816(float* c, const uint32_t* a, const uint32_t* b) {
    asm volatile(
        "mma.sync.aligned.m16n8k16.row.col.f32.bf16.bf16.f32 "
        "{%0,%1,%2,%3}, {%4,%5,%6,%7}, {%8,%9}, {%0,%1,%2,%3};"
        : "+f"(c[0]), "+f"(c[1]), "+f"(c[2]), "+f"(c[3])
        : "r"(a[0]), "r"(a[1]), "r"(a[2]), "r"(a[3]), "r"(b[0]), "r"(b[1]));
}

struct Desc {
    const float* A; int K; int k0; int stream; int hch;
    const __nv_bfloat16* B; int bk0;
};
__device__ __forceinline__ Desc mkdesc(int j, const float* train, const float* agg,
                                       const __nv_bfloat16* wtb) {
    Desc d; d.A = nullptr; d.K = 0; d.k0 = 0; d.stream = 0; d.hch = 0;
    if (j < 16)      { d.stream = 1; d.A = train; d.K = DST_DIM; d.k0 = j * 32;
                       d.B = wtb + 0 * WST; d.bk0 = j * 32; }
    else if (j < 20) { d.stream = 1; d.A = agg;   d.K = 128; d.k0 = (j - 16) * 32;
                       d.B = wtb + 1 * WST; d.bk0 = (j - 16) * 32; }
    else if (j < 24) { d.hch = j - 20; d.B = wtb + 2 * WST; d.bk0 = (j - 20) * 32; }
    else if (j < 28) { d.stream = 1; d.A = agg;   d.K = 128; d.k0 = (j - 24) * 32;
                       d.B = wtb + 3 * WST; d.bk0 = (j - 24) * 32; }
    else if (j < 32) { d.hch = j - 28; d.B = wtb + 4 * WST; d.bk0 = (j - 28) * 32; }
    else             { d.hch = j - 32; d.B = wtb + 5 * WST; d.bk0 = (j - 32) * 32; }
    return d;
}

template <int NJJ>
__device__ __forceinline__ void mma_chunk(const char* Ab, const char* Bb,
                                          int warp_m, int warp_n, int lane,
                                          float (&c)[4][8][4]) {
    #pragma unroll
    for (int term = 0; term < 3; ++term) {
        const __nv_bfloat16* Ap = (const __nv_bfloat16*)(Ab + (term == 2 ? PLANE_B : 0));
        const __nv_bfloat16* Bp = (const __nv_bfloat16*)(Bb + (term == 1 ? PLANE_B : 0));
        #pragma unroll
        for (int h = 0; h < 2; ++h) {
            const int kb = h * 16 + (lane & 3) * 2;
            uint32_t a[4][4], b[NJJ][2];
            #pragma unroll
            for (int i = 0; i < 4; ++i) {
                const __nv_bfloat16* p = Ap + (warp_m * 64 + i * 16 + (lane >> 2)) * SP + kb;
                a[i][0] = *(const uint32_t*)p;
                a[i][1] = *(const uint32_t*)(p + 8 * SP);
                a[i][2] = *(const uint32_t*)(p + 8);
                a[i][3] = *(const uint32_t*)(p + 8 * SP + 8);
            }
            #pragma unroll
            for (int jj = 0; jj < NJJ; ++jj) {
                const __nv_bfloat16* p = Bp + (warp_n * 64 + jj * 8 + (lane >> 2)) * SP + kb;
                b[jj][0] = *(const uint32_t*)p;
                b[jj][1] = *(const uint32_t*)(p + 8);
            }
            #pragma unroll
            for (int i = 0; i < 4; ++i)
                #pragma unroll
                for (int jj = 0; jj < NJJ; ++jj)
                    mma16816(c[i][jj], a[i], b[jj]);
        }
    }
}

// epilogue: relu(c+bias) -> bf16 hi/lo H tiles; clears c
__device__ __forceinline__ void epi_to_H(float (&c)[4][8][4], const float* bias,
                                         char* smem, int warp_m, int warp_n, int lane) {
    __syncthreads();   // all warps done reading smem tiles for this layer
    #pragma unroll
    for (int i = 0; i < 4; ++i) {
        #pragma unroll
        for (int jj = 0; jj < 8; ++jj) {
            int col = warp_n * 64 + jj * 8 + (lane & 3) * 2;
            int ch = col >> 5, kk = col & 31;
            float b0 = __ldg(&bias[col]), b1 = __ldg(&bias[col + 1]);
            #pragma unroll
            for (int rh = 0; rh < 2; ++rh) {
                int row = warp_m * 64 + i * 16 + (lane >> 2) + rh * 8;
                float v0 = fmaxf(c[i][jj][rh * 2 + 0] + b0, 0.f);
                float v1 = fmaxf(c[i][jj][rh * 2 + 1] + b1, 0.f);
                __nv_bfloat16 h0 = __float2bfloat16_rn(v0);
                __nv_bfloat16 h1 = __float2bfloat16_rn(v1);
                float l0 = v0 - __bfloat162float(h0);
                float l1 = v1 - __bfloat162float(h1);
                __nv_bfloat162 hp = __halves2bfloat162(h0, h1);
                __nv_bfloat162 lp = __halves2bfloat162(__float2bfloat16_rn(l0),
                                                       __float2bfloat16_rn(l1));
                *(__nv_bfloat162*)(smem + OFF_H + (ch * 2 + 0) * PLANE_B + (row * SP + kk) * 2) = hp;
                *(__nv_bfloat162*)(smem + OFF_H + (ch * 2 + 1) * PLANE_B + (row * SP + kk) * 2) = lp;
                c[i][jj][rh * 2 + 0] = 0.f;
                c[i][jj][rh * 2 + 1] = 0.f;
            }
        }
    }
}

__global__ void __launch_bounds__(128, 1) k_fused(
    const float* __restrict__ train, const float* __restrict__ agg,
    const __nv_bfloat16* __restrict__ wtb,
    const float* __restrict__ b1, const float* __restrict__ b2,
    const float* __restrict__ bc1, const float* __restrict__ bc2,
    float* __restrict__ outp)
{
    extern __shared__ __align__(16) char smem[];
    const int tid    = threadIdx.x;
    const int lane   = tid & 31;
    const int wid    = tid >> 5;
    const int warp_m = wid >> 1;
    const int warp_n = wid & 1;
    const int m0     = blockIdx.x * 128;

    const uint32_t afp_u = smem_u32(smem + OFF_AFP);
    const uint32_t bs_u  = smem_u32(smem + OFF_BS);
    float* Afp = (float*)(smem + OFF_AFP);

    float c[4][8][4];
    #pragma unroll
    for (int i = 0; i < 4; ++i)
        #pragma unroll
        for (int j = 0; j < 8; ++j)
            #pragma unroll
            for (int q = 0; q < 4; ++q) c[i][j][q] = 0.f;

    auto issue = [&](int cj, int stage) {
        Desc d = mkdesc(cj, train, agg, wtb);
        if (d.stream) {
            #pragma unroll
            for (int i = 0; i < 8; ++i) {
                int idx = i * 128 + tid;
                int row = idx >> 3, cc = idx & 7;
                int gr = m0 + row, k = d.k0 + cc * 4;
                int nb = 0;
                if (gr < NT) { int rem = d.K - k; nb = (rem >= 4) ? 16 : (rem > 0 ? rem * 4 : 0); }
                const float* src = nb ? (d.A + (size_t)gr * d.K + k) : d.A;
                CP16Z(afp_u + row * 144 + cc * 16, src, nb);
            }
        }
        CP_COMMIT();   // A group (possibly empty)
        #pragma unroll
        for (int p = 0; p < 2; ++p) {
            const __nv_bfloat16* bp = d.B + (size_t)p * 128 * 512;
            uint32_t bd = bs_u + (stage * 2 + p) * PLANE_B;
            #pragma unroll
            for (int i = 0; i < 4; ++i) {
                int idx = i * 128 + tid;
                int n = idx >> 2, cc = idx & 3;
                CP16(bd + n * 80 + cc * 16, bp + (size_t)n * 512 + d.bk0 + cc * 8);
            }
        }
        CP_COMMIT();   // B group
    };

    issue(0, 0);

    for (int j = 0; j < 36; ++j) {
        const int s = j & 1;
        Desc d = mkdesc(j, train, agg, wtb);

        CP_WAIT1();             // A(j) done
        __syncthreads();
        if (d.stream) {
            // convert fp32 staging -> bf16 hi/lo Astage[s]
            __nv_bfloat16* Ah = (__nv_bfloat16*)(smem + OFF_AST + (s * 2 + 0) * PLANE_B);
            __nv_bfloat16* Al = (__nv_bfloat16*)(smem + OFF_AST + (s * 2 + 1) * PLANE_B);
            const float* ar = Afp + tid * 36;
            uint32_t hp[16], lp[16];
            #pragma unroll
            for (int cc = 0; cc < 8; ++cc) {
                float4 f = *(const float4*)(ar + cc * 4);
                __nv_bfloat16 h0 = __float2bfloat16_rn(f.x);
                __nv_bfloat16 h1 = __float2bfloat16_rn(f.y);
                __nv_bfloat16 h2 = __float2bfloat16_rn(f.z);
                __nv_bfloat16 h3 = __float2bfloat16_rn(f.w);
                float l0 = f.x - __bfloat162float(h0);
                float l1 = f.y - __bfloat162float(h1);
                float l2 = f.z - __bfloat162float(h2);
                float l3 = f.w - __bfloat162float(h3);
                __nv_bfloat162 ph0 = __halves2bfloat162(h0, h1);
                __nv_bfloat162 ph1 = __halves2bfloat162(h2, h3);
                __nv_bfloat162 pl0 = __halves2bfloat162(__float2bfloat16_rn(l0), __float2bfloat16_rn(l1));
                __nv_bfloat162 pl1 = __halves2bfloat162(__float2bfloat16_rn(l2), __float2bfloat16_rn(l3));
                hp[cc * 2 + 0] = *(uint32_t*)&ph0;
                hp[cc * 2 + 1] = *(uint32_t*)&ph1;
                lp[cc * 2 + 0] = *(uint32_t*)&pl0;
                lp[cc * 2 + 1] = *(uint32_t*)&pl1;
            }
            uint32_t* dh = (uint32_t*)(Ah + tid * SP);
            uint32_t* dl = (uint32_t*)(Al + tid * SP);
            #pragma unroll
            for (int cc = 0; cc < 4; ++cc) {
                *(uint4*)(dh + cc * 4) = *(uint4*)(hp + cc * 4);
                *(uint4*)(dl + cc * 4) = *(uint4*)(lp + cc * 4);
            }
        }
        CP_WAIT0();             // B(j) done
        __syncthreads();

        if (j + 1 < 36) issue(j + 1, (j + 1) & 1);

        const char* Ab = d.stream ? (smem + OFF_AST + s * 2 * PLANE_B)
                                  : (smem + OFF_H + d.hch * 2 * PLANE_B);
        const char* Bb = smem + OFF_BS + s * 2 * PLANE_B;

        if (j < 32)           mma_chunk<8>(Ab, Bb, warp_m, warp_n, lane, c);
        else if (warp_n == 0) mma_chunk<2>(Ab, Bb, warp_m, warp_n, lane, c);

        if (j == 19)      epi_to_H(c, b1, smem, warp_m, warp_n, lane);
        else if (j == 27) epi_to_H(c, b2, smem, warp_m, warp_n, lane);
        else if (j == 31) epi_to_H(c, bc1, smem, warp_m, warp_n, lane);
    }

    // ---- cls store: out[NT,16] = c + bc2 (warp_n==0 warps hold cols 0..15) ----
    if (warp_n == 0) {
        #pragma unroll
        for (int i = 0; i < 4; ++i) {
            #pragma unroll
            for (int jj = 0; jj < 2; ++jj) {
                int col = jj * 8 + (lane & 3) * 2;
                float b0 = __ldg(&bc2[col]), b1 = __ldg(&bc2[col + 1]);
                #pragma unroll
                for (int rh = 0; rh < 2; ++rh) {
                    int row = m0 + warp_m * 64 + i * 16 + (lane >> 2) + rh * 8;
                    if (row < NT) {
                        float2 v = make_float2(c[i][jj][rh * 2 + 0] + b0,
                                               c[i][jj][rh * 2 + 1] + b1);
                        *(float2*)(outp + (size_t)row * NCLS + col) = v;
                    }
                }
            }
        }
    }
}

// ---------------- launch ----------------
extern "C" void kernel_launch(void* const* d_in, const int* in_sizes, int n_in,
                              void* d_out, int out_size)
{
    const float* gene  = (const float*)d_in[0];
    const float* train = (const float*)d_in[1];
    const int*   esrc  = (const int*)  d_in[2];
    const int*   edst  = (const int*)  d_in[3];
    const float* W1n   = (const float*)d_in[4];
    const float* W1s   = (const float*)d_in[5];
    const float* b1    = (const float*)d_in[6];
    const float* W2n   = (const float*)d_in[7];
    const float* W2s   = (const float*)d_in[8];
    const float* b2    = (const float*)d_in[9];
    const float* Wc1   = (const float*)d_in[10];
    const float* bc1   = (const float*)d_in[11];
    const float* Wc2   = (const float*)d_in[12];
    const float* bc2   = (const float*)d_in[13];
    float* out = (float*)d_out;

    float* agg;
    __nv_bfloat16* wtb;
    cudaGetSymbolAddress((void**)&agg, g_agg);
    cudaGetSymbolAddress((void**)&wtb, g_wtb);

    static bool attr_done = false;
    if (!attr_done) {
        cudaFuncSetAttribute(k_fused, cudaFuncAttributeMaxDynamicSharedMemorySize, SMEM_FUSED);
        attr_done = true;
    }

    k_trh<<<(6 * 65536 + 255) / 256, 256>>>(W1s, W1n, W2s, W2n, Wc1, Wc2, edst);
    k_scan<<<1, 1024>>>();
    k_scatter<<<(NE / 2 + 255) / 256, 256>>>(esrc, edst);
    k_spmm<<<(NT * 32 + 255) / 256, 256>>>(gene);
    k_fused<<<(NT + 127) / 128, 128, SMEM_FUSED>>>(train, agg, wtb, b1, b2, bc1, bc2, out);

    (void)in_sizes; (void)n_in; (void)out_size;
}

// round 9
// speedup vs baseline: 1.0024x; 1.0024x over previous
#include <cuda_runtime.h>
#include <cuda_bf16.h>
#include <cstdint>

static constexpr int NG      = 2500;
static constexpr int NT      = 20000;
static constexpr int NE      = 640000;
static constexpr int SRC_DIM = 128;
static constexpr int DST_DIM = 500;
static constexpr int HID     = 128;
static constexpr int OUTD    = 128;
static constexpr int NCLS    = 16;

// ---------------- scratch (device globals: no allocation allowed) ----------------
__device__ float g_agg[NT * SRC_DIM];
__device__ int   g_deg[NT];          // zero-init at load; re-zeroed by k_scan each run
__device__ int   g_rowptr[NT + 1];
__device__ int   g_cursor[NT];
__device__ int   g_colidx[NE];
// weights as bf16 hi/lo planes: [w(6)][plane(2)][n(128)][k(512 padded)]
__device__ __nv_bfloat16 g_wtb[6 * 2 * 128 * 512];

static constexpr size_t WST = (size_t)2 * 128 * 512;   // slot stride in elements

// ---------------- k_trh: weight transpose + bf16 split + edge histogram ----------------
__global__ void k_trh(const float* __restrict__ W1s, const float* __restrict__ W1n,
                      const float* __restrict__ W2s, const float* __restrict__ W2n,
                      const float* __restrict__ Wc1, const float* __restrict__ Wc2,
                      const int* __restrict__ edst) {
    int t = blockIdx.x * blockDim.x + threadIdx.x;
    int e0 = t * 2;
    if (e0 < NE)     atomicAdd(&g_deg[__ldg(&edst[e0])], 1);
    if (e0 + 1 < NE) atomicAdd(&g_deg[__ldg(&edst[e0 + 1])], 1);

    if (t >= 6 * 65536) return;
    int w   = t >> 16;
    int rem = t & 65535;
    int n   = rem >> 9;
    int k   = rem & 511;
    float v = 0.f;
    if (w == 0)      { if (k < DST_DIM) v = W1s[(size_t)k * 128 + n]; }
    else if (w == 1) { if (k < 128)     v = W1n[(size_t)k * 128 + n]; }
    else if (w == 2) { if (k < 128)     v = W2s[(size_t)k * 128 + n]; }
    else if (w == 3) { if (k < 128)     v = W2n[(size_t)k * 128 + n]; }
    else if (w == 4) { if (k < 128)     v = Wc1[(size_t)k * 128 + n]; }
    else             { if (k < 128 && n < NCLS) v = Wc2[(size_t)k * NCLS + n]; }
    __nv_bfloat16 hb = __float2bfloat16_rn(v);
    float lo = v - __bfloat162float(hb);
    g_wtb[(size_t)w * WST + (size_t)n * 512 + k] = hb;
    g_wtb[(size_t)w * WST + 128 * 512 + (size_t)n * 512 + k] = __float2bfloat16_rn(lo);
}

// ---------------- single-pass scan (also re-zeros g_deg for the next replay) ----------------
__global__ void __launch_bounds__(1024) k_scan() {
    constexpr int PER = 20;
    __shared__ int wsum[32];
    const int tid  = threadIdx.x;
    const int lane = tid & 31;
    const int wid  = tid >> 5;
    const int base = tid * PER;

    int pref[PER];
    int s = 0;
    #pragma unroll
    for (int q = 0; q < PER; ++q) {
        int i = base + q;
        int d = 0;
        if (i < NT) { d = g_deg[i]; g_deg[i] = 0; }
        pref[q] = s;
        s += d;
    }
    int x = s;
    #pragma unroll
    for (int off = 1; off < 32; off <<= 1) {
        int y = __shfl_up_sync(0xffffffffu, x, off);
        if (lane >= off) x += y;
    }
    if (lane == 31) wsum[wid] = x;
    __syncthreads();
    if (wid == 0) {
        int w = wsum[lane];
        #pragma unroll
        for (int off = 1; off < 32; off <<= 1) {
            int y = __shfl_up_sync(0xffffffffu, w, off);
            if (lane >= off) w += y;
        }
        wsum[lane] = w;
    }
    __syncthreads();
    const int tbase = (x - s) + (wid ? wsum[wid - 1] : 0);
    #pragma unroll
    for (int q = 0; q < PER; ++q) {
        int i = base + q;
        if (i < NT) {
            int rp = tbase + pref[q];
            g_rowptr[i] = rp;
            g_cursor[i] = rp;
        }
    }
    if (tid == 1023) g_rowptr[NT] = tbase + s;
}

// 8 edges per thread: independent atomic chains raise MLP
__global__ void k_scatter(const int* __restrict__ src, const int* __restrict__ dst) {
    int e0 = (blockIdx.x * blockDim.x + threadIdx.x) * 8;
    #pragma unroll
    for (int q = 0; q < 8; ++q) {
        int e = e0 + q;
        if (e < NE) {
            int p = atomicAdd(&g_cursor[__ldg(&dst[e])], 1);
            g_colidx[p] = __ldg(&src[e]);
        }
    }
}

// ---------------- SpMM mean: one warp per dst row ----------------
__global__ void __launch_bounds__(256) k_spmm(const float* __restrict__ gene) {
    int row  = (blockIdx.x * blockDim.x + threadIdx.x) >> 5;
    int lane = threadIdx.x & 31;
    if (row >= NT) return;
    int beg = g_rowptr[row];
    int end = g_rowptr[row + 1];
    float4 a = make_float4(0.f, 0.f, 0.f, 0.f);
    for (int base = beg; base < end; base += 32) {
        int myidx = (base + lane < end) ? g_colidx[base + lane] : 0;
        int cnt = min(32, end - base);
        int j = 0;
        for (; j + 4 <= cnt; j += 4) {
            int s0 = __shfl_sync(0xffffffffu, myidx, j);
            int s1 = __shfl_sync(0xffffffffu, myidx, j + 1);
            int s2 = __shfl_sync(0xffffffffu, myidx, j + 2);
            int s3 = __shfl_sync(0xffffffffu, myidx, j + 3);
            float4 v0 = *((const float4*)(gene + (size_t)s0 * SRC_DIM) + lane);
            float4 v1 = *((const float4*)(gene + (size_t)s1 * SRC_DIM) + lane);
            float4 v2 = *((const float4*)(gene + (size_t)s2 * SRC_DIM) + lane);
            float4 v3 = *((const float4*)(gene + (size_t)s3 * SRC_DIM) + lane);
            a.x += v0.x + v1.x + v2.x + v3.x;
            a.y += v0.y + v1.y + v2.y + v3.y;
            a.z += v0.z + v1.z + v2.z + v3.z;
            a.w += v0.w + v1.w + v2.w + v3.w;
        }
        for (; j < cnt; ++j) {
            int s = __shfl_sync(0xffffffffu, myidx, j);
            float4 v = *((const float4*)(gene + (size_t)s * SRC_DIM) + lane);
            a.x += v.x; a.y += v.y; a.z += v.z; a.w += v.w;
        }
    }
    float inv = 1.0f / (float)max(end - beg, 1);
    a.x *= inv; a.y *= inv; a.z *= inv; a.w *= inv;
    *((float4*)(g_agg + (size_t)row * SRC_DIM) + lane) = a;
}

// ---------------- fused 4-layer network kernel (256 threads, 8 warps) ----------------
static constexpr int SP      = 40;                 // bf16 tile pitch (80B, conflict-free)
static constexpr int PLANE_B = 128 * SP * 2;       // 10240 B per (chunk,plane) tile
static constexpr int OFF_H   = 0;                  // H[ch(4)][plane(2)]
static constexpr int OFF_AST = 8 * PLANE_B;        // Astage[s(2)][plane(2)]
static constexpr int OFF_BS  = OFF_AST + 4 * PLANE_B;  // Bs[s(2)][plane(2)]
static constexpr int OFF_AFP = OFF_BS + 4 * PLANE_B;   // fp32 staging 128 x 36 floats
static constexpr int SMEM_FUSED = OFF_AFP + 128 * 144; // 182272

__device__ __forceinline__ uint32_t smem_u32(const void* p) {
    uint32_t a;
    asm("{ .reg .u64 t; cvta.to.shared.u64 t, %1; cvt.u32.u64 %0, t; }" : "=r"(a) : "l"(p));
    return a;
}
#define CP16(dst, src) \
    asm volatile("cp.async.ca.shared.global [%0], [%1], 16;" :: "r"(dst), "l"(src))
#define CP16Z(dst, src, nb) \
    asm volatile("cp.async.ca.shared.global [%0], [%1], 16, %2;" :: "r"(dst), "l"(src), "r"(nb))
#define CP_COMMIT() asm volatile("cp.async.commit_group;" ::: "memory")
#define CP_WAIT1()  asm volatile("cp.async.wait_group 1;" ::: "memory")
#define CP_WAIT0()  asm volatile("cp.async.wait_group 0;" ::: "memory")

__device__ __forceinline__ void mma16816(float* c, const uint32_t* a, const uint32_t* b) {
    asm volatile(
        "mma.sync.aligned.m16n8k16.row.col.f32.bf16.bf16.f32 "
        "{%0,%1,%2,%3}, {%4,%5,%6,%7}, {%8,%9}, {%0,%1,%2,%3};"
        : "+f"(c[0]), "+f"(c[1]), "+f"(c[2]), "+f"(c[3])
        : "r"(a[0]), "r"(a[1]), "r"(a[2]), "r"(a[3]), "r"(b[0]), "r"(b[1]));
}

struct Desc {
    const float* A; int K; int k0; int stream; int hch;
    const __nv_bfloat16* B; int bk0;
};
__device__ __forceinline__ Desc mkdesc(int j, const float* train, const float* agg,
                                       const __nv_bfloat16* wtb) {
    Desc d; d.A = nullptr; d.K = 0; d.k0 = 0; d.stream = 0; d.hch = 0;
    if (j < 16)      { d.stream = 1; d.A = train; d.K = DST_DIM; d.k0 = j * 32;
                       d.B = wtb + 0 * WST; d.bk0 = j * 32; }
    else if (j < 20) { d.stream = 1; d.A = agg;   d.K = 128; d.k0 = (j - 16) * 32;
                       d.B = wtb + 1 * WST; d.bk0 = (j - 16) * 32; }
    else if (j < 24) { d.hch = j - 20; d.B = wtb + 2 * WST; d.bk0 = (j - 20) * 32; }
    else if (j < 28) { d.stream = 1; d.A = agg;   d.K = 128; d.k0 = (j - 24) * 32;
                       d.B = wtb + 3 * WST; d.bk0 = (j - 24) * 32; }
    else if (j < 32) { d.hch = j - 28; d.B = wtb + 4 * WST; d.bk0 = (j - 28) * 32; }
    else             { d.hch = j - 32; d.B = wtb + 5 * WST; d.bk0 = (j - 32) * 32; }
    return d;
}

// warp tile 32x64: c[2][NJJ][4]
template <int NJJ>
__device__ __forceinline__ void mma_chunk(const char* Ab, const char* Bb,
                                          int warp_m, int warp_n, int lane,
                                          float (&c)[2][8][4]) {
    #pragma unroll
    for (int term = 0; term < 3; ++term) {
        const __nv_bfloat16* Ap = (const __nv_bfloat16*)(Ab + (term == 2 ? PLANE_B : 0));
        const __nv_bfloat16* Bp = (const __nv_bfloat16*)(Bb + (term == 1 ? PLANE_B : 0));
        #pragma unroll
        for (int h = 0; h < 2; ++h) {
            const int kb = h * 16 + (lane & 3) * 2;
            uint32_t a[2][4], b[NJJ][2];
            #pragma unroll
            for (int i = 0; i < 2; ++i) {
                const __nv_bfloat16* p = Ap + (warp_m * 32 + i * 16 + (lane >> 2)) * SP + kb;
                a[i][0] = *(const uint32_t*)p;
                a[i][1] = *(const uint32_t*)(p + 8 * SP);
                a[i][2] = *(const uint32_t*)(p + 8);
                a[i][3] = *(const uint32_t*)(p + 8 * SP + 8);
            }
            #pragma unroll
            for (int jj = 0; jj < NJJ; ++jj) {
                const __nv_bfloat16* p = Bp + (warp_n * 64 + jj * 8 + (lane >> 2)) * SP + kb;
                b[jj][0] = *(const uint32_t*)p;
                b[jj][1] = *(const uint32_t*)(p + 8);
            }
            #pragma unroll
            for (int i = 0; i < 2; ++i)
                #pragma unroll
                for (int jj = 0; jj < NJJ; ++jj)
                    mma16816(c[i][jj], a[i], b[jj]);
        }
    }
}

// epilogue: relu(c+bias) -> bf16 hi/lo H tiles; clears c
__device__ __forceinline__ void epi_to_H(float (&c)[2][8][4], const float* bias,
                                         char* smem, int warp_m, int warp_n, int lane) {
    __syncthreads();   // all warps done reading smem tiles for this layer
    #pragma unroll
    for (int i = 0; i < 2; ++i) {
        #pragma unroll
        for (int jj = 0; jj < 8; ++jj) {
            int col = warp_n * 64 + jj * 8 + (lane & 3) * 2;
            int ch = col >> 5, kk = col & 31;
            float b0 = __ldg(&bias[col]), b1 = __ldg(&bias[col + 1]);
            #pragma unroll
            for (int rh = 0; rh < 2; ++rh) {
                int row = warp_m * 32 + i * 16 + (lane >> 2) + rh * 8;
                float v0 = fmaxf(c[i][jj][rh * 2 + 0] + b0, 0.f);
                float v1 = fmaxf(c[i][jj][rh * 2 + 1] + b1, 0.f);
                __nv_bfloat16 h0 = __float2bfloat16_rn(v0);
                __nv_bfloat16 h1 = __float2bfloat16_rn(v1);
                float l0 = v0 - __bfloat162float(h0);
                float l1 = v1 - __bfloat162float(h1);
                __nv_bfloat162 hp = __halves2bfloat162(h0, h1);
                __nv_bfloat162 lp = __halves2bfloat162(__float2bfloat16_rn(l0),
                                                       __float2bfloat16_rn(l1));
                *(__nv_bfloat162*)(smem + OFF_H + (ch * 2 + 0) * PLANE_B + (row * SP + kk) * 2) = hp;
                *(__nv_bfloat162*)(smem + OFF_H + (ch * 2 + 1) * PLANE_B + (row * SP + kk) * 2) = lp;
                c[i][jj][rh * 2 + 0] = 0.f;
                c[i][jj][rh * 2 + 1] = 0.f;
            }
        }
    }
}

__global__ void __launch_bounds__(256, 1) k_fused(
    const float* __restrict__ train, const float* __restrict__ agg,
    const __nv_bfloat16* __restrict__ wtb,
    const float* __restrict__ b1, const float* __restrict__ b2,
    const float* __restrict__ bc1, const float* __restrict__ bc2,
    float* __restrict__ outp)
{
    extern __shared__ __align__(16) char smem[];
    const int tid    = threadIdx.x;
    const int lane   = tid & 31;
    const int wid    = tid >> 5;
    const int warp_m = wid >> 1;     // 0..3 -> 32-row band
    const int warp_n = wid & 1;      // 0..1 -> 64-col band
    const int m0     = blockIdx.x * 128;

    const uint32_t afp_u = smem_u32(smem + OFF_AFP);
    const uint32_t bs_u  = smem_u32(smem + OFF_BS);
    float* Afp = (float*)(smem + OFF_AFP);

    float c[2][8][4];
    #pragma unroll
    for (int i = 0; i < 2; ++i)
        #pragma unroll
        for (int j = 0; j < 8; ++j)
            #pragma unroll
            for (int q = 0; q < 4; ++q) c[i][j][q] = 0.f;

    auto issue = [&](int cj, int stage) {
        Desc d = mkdesc(cj, train, agg, wtb);
        if (d.stream) {
            #pragma unroll
            for (int i = 0; i < 4; ++i) {
                int idx = i * 256 + tid;
                int row = idx >> 3, cc = idx & 7;
                int gr = m0 + row, k = d.k0 + cc * 4;
                int nb = 0;
                if (gr < NT) { int rem = d.K - k; nb = (rem >= 4) ? 16 : (rem > 0 ? rem * 4 : 0); }
                const float* src = nb ? (d.A + (size_t)gr * d.K + k) : d.A;
                CP16Z(afp_u + row * 144 + cc * 16, src, nb);
            }
        }
        CP_COMMIT();   // A group (possibly empty)
        #pragma unroll
        for (int p = 0; p < 2; ++p) {
            const __nv_bfloat16* bp = d.B + (size_t)p * 128 * 512;
            uint32_t bd = bs_u + (stage * 2 + p) * PLANE_B;
            #pragma unroll
            for (int i = 0; i < 2; ++i) {
                int idx = i * 256 + tid;
                int n = idx >> 2, cc = idx & 3;
                CP16(bd + n * 80 + cc * 16, bp + (size_t)n * 512 + d.bk0 + cc * 8);
            }
        }
        CP_COMMIT();   // B group
    };

    issue(0, 0);

    for (int j = 0; j < 36; ++j) {
        const int s = j & 1;
        Desc d = mkdesc(j, train, agg, wtb);

        CP_WAIT1();             // A(j) done
        __syncthreads();
        if (d.stream && tid < 128) {
            // convert fp32 staging -> bf16 hi/lo Astage[s]; one thread per row
            __nv_bfloat16* Ah = (__nv_bfloat16*)(smem + OFF_AST + (s * 2 + 0) * PLANE_B);
            __nv_bfloat16* Al = (__nv_bfloat16*)(smem + OFF_AST + (s * 2 + 1) * PLANE_B);
            const float* ar = Afp + tid * 36;
            uint32_t hp[16], lp[16];
            #pragma unroll
            for (int cc = 0; cc < 8; ++cc) {
                float4 f = *(const float4*)(ar + cc * 4);
                __nv_bfloat16 h0 = __float2bfloat16_rn(f.x);
                __nv_bfloat16 h1 = __float2bfloat16_rn(f.y);
                __nv_bfloat16 h2 = __float2bfloat16_rn(f.z);
                __nv_bfloat16 h3 = __float2bfloat16_rn(f.w);
                float l0 = f.x - __bfloat162float(h0);
                float l1 = f.y - __bfloat162float(h1);
                float l2 = f.z - __bfloat162float(h2);
                float l3 = f.w - __bfloat162float(h3);
                __nv_bfloat162 ph0 = __halves2bfloat162(h0, h1);
                __nv_bfloat162 ph1 = __halves2bfloat162(h2, h3);
                __nv_bfloat162 pl0 = __halves2bfloat162(__float2bfloat16_rn(l0), __float2bfloat16_rn(l1));
                __nv_bfloat162 pl1 = __halves2bfloat162(__float2bfloat16_rn(l2), __float2bfloat16_rn(l3));
                hp[cc * 2 + 0] = *(uint32_t*)&ph0;
                hp[cc * 2 + 1] = *(uint32_t*)&ph1;
                lp[cc * 2 + 0] = *(uint32_t*)&pl0;
                lp[cc * 2 + 1] = *(uint32_t*)&pl1;
            }
            uint32_t* dh = (uint32_t*)(Ah + tid * SP);
            uint32_t* dl = (uint32_t*)(Al + tid * SP);
            #pragma unroll
            for (int cc = 0; cc < 4; ++cc) {
                *(uint4*)(dh + cc * 4) = *(uint4*)(hp + cc * 4);
                *(uint4*)(dl + cc * 4) = *(uint4*)(lp + cc * 4);
            }
        }
        CP_WAIT0();             // B(j) done
        __syncthreads();

        if (j + 1 < 36) issue(j + 1, (j + 1) & 1);

        const char* Ab = d.stream ? (smem + OFF_AST + s * 2 * PLANE_B)
                                  : (smem + OFF_H + d.hch * 2 * PLANE_B);
        const char* Bb = smem + OFF_BS + s * 2 * PLANE_B;

        if (j < 32)           mma_chunk<8>(Ab, Bb, warp_m, warp_n, lane, c);
        else if (warp_n == 0) mma_chunk<2>(Ab, Bb, warp_m, warp_n, lane, c);

        if (j == 19)      epi_to_H(c, b1, smem, warp_m, warp_n, lane);
        else if (j == 27) epi_to_H(c, b2, smem, warp_m, warp_n, lane);
        else if (j == 31) epi_to_H(c, bc1, smem, warp_m, warp_n, lane);
    }

    // ---- cls store: out[NT,16] = c + bc2 (warp_n==0 warps hold cols 0..15) ----
    if (warp_n == 0) {
        #pragma unroll
        for (int i = 0; i < 2; ++i) {
            #pragma unroll
            for (int jj = 0; jj < 2; ++jj) {
                int col = jj * 8 + (lane & 3) * 2;
                float b0 = __ldg(&bc2[col]), b1 = __ldg(&bc2[col + 1]);
                #pragma unroll
                for (int rh = 0; rh < 2; ++rh) {
                    int row = m0 + warp_m * 32 + i * 16 + (lane >> 2) + rh * 8;
                    if (row < NT) {
                        float2 v = make_float2(c[i][jj][rh * 2 + 0] + b0,
                                               c[i][jj][rh * 2 + 1] + b1);
                        *(float2*)(outp + (size_t)row * NCLS + col) = v;
                    }
                }
            }
        }
    }
}

// ---------------- launch ----------------
extern "C" void kernel_launch(void* const* d_in, const int* in_sizes, int n_in,
                              void* d_out, int out_size)
{
    const float* gene  = (const float*)d_in[0];
    const float* train = (const float*)d_in[1];
    const int*   esrc  = (const int*)  d_in[2];
    const int*   edst  = (const int*)  d_in[3];
    const float* W1n   = (const float*)d_in[4];
    const float* W1s   = (const float*)d_in[5];
    const float* b1    = (const float*)d_in[6];
    const float* W2n   = (const float*)d_in[7];
    const float* W2s   = (const float*)d_in[8];
    const float* b2    = (const float*)d_in[9];
    const float* Wc1   = (const float*)d_in[10];
    const float* bc1   = (const float*)d_in[11];
    const float* Wc2   = (const float*)d_in[12];
    const float* bc2   = (const float*)d_in[13];
    float* out = (float*)d_out;

    float* agg;
    __nv_bfloat16* wtb;
    cudaGetSymbolAddress((void**)&agg, g_agg);
    cudaGetSymbolAddress((void**)&wtb, g_wtb);

    static bool attr_done = false;
    if (!attr_done) {
        cudaFuncSetAttribute(k_fused, cudaFuncAttributeMaxDynamicSharedMemorySize, SMEM_FUSED);
        attr_done = true;
    }

    k_trh<<<(6 * 65536 + 255) / 256, 256>>>(W1s, W1n, W2s, W2n, Wc1, Wc2, edst);
    k_scan<<<1, 1024>>>();
    k_scatter<<<(NE / 8 + 255) / 256, 256>>>(esrc, edst);
    k_spmm<<<(NT * 32 + 255) / 256, 256>>>(gene);
    k_fused<<<(NT + 127) / 128, 256, SMEM_FUSED>>>(train, agg, wtb, b1, b2, bc1, bc2, out);

    (void)in_sizes; (void)n_in; (void)out_size;
}

// round 10
// speedup vs baseline: 1.1539x; 1.1512x over previous
#include <cuda_runtime.h>
#include <cuda_bf16.h>
#include <cstdint>

static constexpr int NG      = 2500;
static constexpr int NT      = 20000;
static constexpr int NE      = 640000;
static constexpr int SRC_DIM = 128;
static constexpr int DST_DIM = 500;
static constexpr int HID     = 128;
static constexpr int OUTD    = 128;
static constexpr int NCLS    = 16;

// ---------------- scratch (device globals: no allocation allowed) ----------------
__device__ float g_agg[NT * SRC_DIM];
__device__ int   g_deg[NT];          // zero-init at load; re-zeroed by k_scan each run
__device__ int   g_rowptr[NT + 1];
__device__ int   g_cursor[NT];
__device__ int   g_colidx[NE];
// weights as bf16 hi/lo planes: [w(6)][plane(2)][n(128)][k(512 padded)]
__device__ __nv_bfloat16 g_wtb[6 * 2 * 128 * 512];

static constexpr size_t WST = (size_t)2 * 128 * 512;   // slot stride in elements

// ---------------- k_trh: weight transpose + bf16 split + edge histogram ----------------
__global__ void k_trh(const float* __restrict__ W1s, const float* __restrict__ W1n,
                      const float* __restrict__ W2s, const float* __restrict__ W2n,
                      const float* __restrict__ Wc1, const float* __restrict__ Wc2,
                      const int* __restrict__ edst) {
    int t = blockIdx.x * blockDim.x + threadIdx.x;
    int e0 = t * 2;
    if (e0 < NE)     atomicAdd(&g_deg[__ldg(&edst[e0])], 1);
    if (e0 + 1 < NE) atomicAdd(&g_deg[__ldg(&edst[e0 + 1])], 1);

    if (t >= 6 * 65536) return;
    int w   = t >> 16;
    int rem = t & 65535;
    int n   = rem >> 9;
    int k   = rem & 511;
    float v = 0.f;
    if (w == 0)      { if (k < DST_DIM) v = W1s[(size_t)k * 128 + n]; }
    else if (w == 1) { if (k < 128)     v = W1n[(size_t)k * 128 + n]; }
    else if (w == 2) { if (k < 128)     v = W2s[(size_t)k * 128 + n]; }
    else if (w == 3) { if (k < 128)     v = W2n[(size_t)k * 128 + n]; }
    else if (w == 4) { if (k < 128)     v = Wc1[(size_t)k * 128 + n]; }
    else             { if (k < 128 && n < NCLS) v = Wc2[(size_t)k * NCLS + n]; }
    __nv_bfloat16 hb = __float2bfloat16_rn(v);
    float lo = v - __bfloat162float(hb);
    g_wtb[(size_t)w * WST + (size_t)n * 512 + k] = hb;
    g_wtb[(size_t)w * WST + 128 * 512 + (size_t)n * 512 + k] = __float2bfloat16_rn(lo);
}

// ---------------- single-pass scan (also re-zeros g_deg for the next replay) ----------------
__global__ void __launch_bounds__(1024) k_scan() {
    constexpr int PER = 20;
    __shared__ int wsum[32];
    const int tid  = threadIdx.x;
    const int lane = tid & 31;
    const int wid  = tid >> 5;
    const int base = tid * PER;

    int pref[PER];
    int s = 0;
    #pragma unroll
    for (int q = 0; q < PER; ++q) {
        int i = base + q;
        int d = 0;
        if (i < NT) { d = g_deg[i]; g_deg[i] = 0; }
        pref[q] = s;
        s += d;
    }
    int x = s;
    #pragma unroll
    for (int off = 1; off < 32; off <<= 1) {
        int y = __shfl_up_sync(0xffffffffu, x, off);
        if (lane >= off) x += y;
    }
    if (lane == 31) wsum[wid] = x;
    __syncthreads();
    if (wid == 0) {
        int w = wsum[lane];
        #pragma unroll
        for (int off = 1; off < 32; off <<= 1) {
            int y = __shfl_up_sync(0xffffffffu, w, off);
            if (lane >= off) w += y;
        }
        wsum[lane] = w;
    }
    __syncthreads();
    const int tbase = (x - s) + (wid ? wsum[wid - 1] : 0);
    #pragma unroll
    for (int q = 0; q < PER; ++q) {
        int i = base + q;
        if (i < NT) {
            int rp = tbase + pref[q];
            g_rowptr[i] = rp;
            g_cursor[i] = rp;
        }
    }
    if (tid == 1023) g_rowptr[NT] = tbase + s;
}

// 8 edges per thread: independent atomic chains raise MLP
__global__ void k_scatter(const int* __restrict__ src, const int* __restrict__ dst) {
    int e0 = (blockIdx.x * blockDim.x + threadIdx.x) * 8;
    #pragma unroll
    for (int q = 0; q < 8; ++q) {
        int e = e0 + q;
        if (e < NE) {
            int p = atomicAdd(&g_cursor[__ldg(&dst[e])], 1);
            g_colidx[p] = __ldg(&src[e]);
        }
    }
}

// ---------------- SpMM mean: one warp per dst row ----------------
__global__ void __launch_bounds__(256) k_spmm(const float* __restrict__ gene) {
    int row  = (blockIdx.x * blockDim.x + threadIdx.x) >> 5;
    int lane = threadIdx.x & 31;
    if (row >= NT) return;
    int beg = g_rowptr[row];
    int end = g_rowptr[row + 1];
    float4 a = make_float4(0.f, 0.f, 0.f, 0.f);
    for (int base = beg; base < end; base += 32) {
        int myidx = (base + lane < end) ? g_colidx[base + lane] : 0;
        int cnt = min(32, end - base);
        int j = 0;
        for (; j + 4 <= cnt; j += 4) {
            int s0 = __shfl_sync(0xffffffffu, myidx, j);
            int s1 = __shfl_sync(0xffffffffu, myidx, j + 1);
            int s2 = __shfl_sync(0xffffffffu, myidx, j + 2);
            int s3 = __shfl_sync(0xffffffffu, myidx, j + 3);
            float4 v0 = *((const float4*)(gene + (size_t)s0 * SRC_DIM) + lane);
            float4 v1 = *((const float4*)(gene + (size_t)s1 * SRC_DIM) + lane);
            float4 v2 = *((const float4*)(gene + (size_t)s2 * SRC_DIM) + lane);
            float4 v3 = *((const float4*)(gene + (size_t)s3 * SRC_DIM) + lane);
            a.x += v0.x + v1.x + v2.x + v3.x;
            a.y += v0.y + v1.y + v2.y + v3.y;
            a.z += v0.z + v1.z + v2.z + v3.z;
            a.w += v0.w + v1.w + v2.w + v3.w;
        }
        for (; j < cnt; ++j) {
            int s = __shfl_sync(0xffffffffu, myidx, j);
            float4 v = *((const float4*)(gene + (size_t)s * SRC_DIM) + lane);
            a.x += v.x; a.y += v.y; a.z += v.z; a.w += v.w;
        }
    }
    float inv = 1.0f / (float)max(end - beg, 1);
    a.x *= inv; a.y *= inv; a.z *= inv; a.w *= inv;
    *((float4*)(g_agg + (size_t)row * SRC_DIM) + lane) = a;
}

// ---------------- fused 4-layer network, 64-row tiles, 2 CTAs/SM ----------------
// Per CTA (64 rows): L0 h1 = relu(train@W1s + agg@W1n + b1)
//                    L1 h2 = relu(h1@W2s + agg@W2n + b2)
//                    L2 h3 = relu(h2@Wc1 + bc1)
//                    L3 out = h3@Wc2 + bc2   (N=16)
static constexpr int MT      = 64;                 // rows per CTA
static constexpr int SP      = 40;                 // bf16 tile pitch (80B, conflict-free)
static constexpr int PLANE_A = MT * SP * 2;        // 5120 B  (A/H plane: 64 rows x 32 k)
static constexpr int PLANE_B = 128 * SP * 2;       // 10240 B (B plane: 128 n x 32 k)
static constexpr int OFF_H   = 0;                              // H[ch(4)][plane(2)]
static constexpr int OFF_AST = OFF_H + 8 * PLANE_A;            // 40960: Ast[s(2)][plane(2)]
static constexpr int OFF_BS  = OFF_AST + 4 * PLANE_A;          // 61440: Bs[s(2)][plane(2)]
static constexpr int OFF_AFP = OFF_BS + 4 * PLANE_B;           // 102400: fp32 64 x 36
static constexpr int SMEM_FUSED = OFF_AFP + MT * 144;          // 111616 -> 2 CTAs/SM

__device__ __forceinline__ uint32_t smem_u32(const void* p) {
    uint32_t a;
    asm("{ .reg .u64 t; cvta.to.shared.u64 t, %1; cvt.u32.u64 %0, t; }" : "=r"(a) : "l"(p));
    return a;
}
#define CP16(dst, src) \
    asm volatile("cp.async.ca.shared.global [%0], [%1], 16;" :: "r"(dst), "l"(src))
#define CP16Z(dst, src, nb) \
    asm volatile("cp.async.ca.shared.global [%0], [%1], 16, %2;" :: "r"(dst), "l"(src), "r"(nb))
#define CP_COMMIT() asm volatile("cp.async.commit_group;" ::: "memory")
#define CP_WAIT1()  asm volatile("cp.async.wait_group 1;" ::: "memory")
#define CP_WAIT0()  asm volatile("cp.async.wait_group 0;" ::: "memory")

__device__ __forceinline__ void mma16816(float* c, const uint32_t* a, const uint32_t* b) {
    asm volatile(
        "mma.sync.aligned.m16n8k16.row.col.f32.bf16.bf16.f32 "
        "{%0,%1,%2,%3}, {%4,%5,%6,%7}, {%8,%9}, {%0,%1,%2,%3};"
        : "+f"(c[0]), "+f"(c[1]), "+f"(c[2]), "+f"(c[3])
        : "r"(a[0]), "r"(a[1]), "r"(a[2]), "r"(a[3]), "r"(b[0]), "r"(b[1]));
}

struct Desc {
    const float* A; int K; int k0; int stream; int hch;
    const __nv_bfloat16* B; int bk0;
};
__device__ __forceinline__ Desc mkdesc(int j, const float* train, const float* agg,
                                       const __nv_bfloat16* wtb) {
    Desc d; d.A = nullptr; d.K = 0; d.k0 = 0; d.stream = 0; d.hch = 0;
    if (j < 16)      { d.stream = 1; d.A = train; d.K = DST_DIM; d.k0 = j * 32;
                       d.B = wtb + 0 * WST; d.bk0 = j * 32; }
    else if (j < 20) { d.stream = 1; d.A = agg;   d.K = 128; d.k0 = (j - 16) * 32;
                       d.B = wtb + 1 * WST; d.bk0 = (j - 16) * 32; }
    else if (j < 24) { d.hch = j - 20; d.B = wtb + 2 * WST; d.bk0 = (j - 20) * 32; }
    else if (j < 28) { d.stream = 1; d.A = agg;   d.K = 128; d.k0 = (j - 24) * 32;
                       d.B = wtb + 3 * WST; d.bk0 = (j - 24) * 32; }
    else if (j < 32) { d.hch = j - 28; d.B = wtb + 4 * WST; d.bk0 = (j - 28) * 32; }
    else             { d.hch = j - 32; d.B = wtb + 5 * WST; d.bk0 = (j - 32) * 32; }
    return d;
}

// warp tile 32x64: c[2][NJJ][4]; A planes stride PLANE_A, B planes stride PLANE_B
template <int NJJ>
__device__ __forceinline__ void mma_chunk(const char* Ab, const char* Bb,
                                          int warp_m, int warp_n, int lane,
                                          float (&c)[2][8][4]) {
    #pragma unroll
    for (int term = 0; term < 3; ++term) {
        const __nv_bfloat16* Ap = (const __nv_bfloat16*)(Ab + (term == 2 ? PLANE_A : 0));
        const __nv_bfloat16* Bp = (const __nv_bfloat16*)(Bb + (term == 1 ? PLANE_B : 0));
        #pragma unroll
        for (int h = 0; h < 2; ++h) {
            const int kb = h * 16 + (lane & 3) * 2;
            uint32_t a[2][4], b[NJJ][2];
            #pragma unroll
            for (int i = 0; i < 2; ++i) {
                const __nv_bfloat16* p = Ap + (warp_m * 32 + i * 16 + (lane >> 2)) * SP + kb;
                a[i][0] = *(const uint32_t*)p;
                a[i][1] = *(const uint32_t*)(p + 8 * SP);
                a[i][2] = *(const uint32_t*)(p + 8);
                a[i][3] = *(const uint32_t*)(p + 8 * SP + 8);
            }
            #pragma unroll
            for (int jj = 0; jj < NJJ; ++jj) {
                const __nv_bfloat16* p = Bp + (warp_n * 64 + jj * 8 + (lane >> 2)) * SP + kb;
                b[jj][0] = *(const uint32_t*)p;
                b[jj][1] = *(const uint32_t*)(p + 8);
            }
            #pragma unroll
            for (int i = 0; i < 2; ++i)
                #pragma unroll
                for (int jj = 0; jj < NJJ; ++jj)
                    mma16816(c[i][jj], a[i], b[jj]);
        }
    }
}

// epilogue: relu(c+bias) -> bf16 hi/lo H tiles; clears c
__device__ __forceinline__ void epi_to_H(float (&c)[2][8][4], const float* bias,
                                         char* smem, int warp_m, int warp_n, int lane) {
    __syncthreads();   // all warps done reading smem tiles for this layer
    #pragma unroll
    for (int i = 0; i < 2; ++i) {
        #pragma unroll
        for (int jj = 0; jj < 8; ++jj) {
            int col = warp_n * 64 + jj * 8 + (lane & 3) * 2;
            int ch = col >> 5, kk = col & 31;
            float b0 = __ldg(&bias[col]), b1 = __ldg(&bias[col + 1]);
            #pragma unroll
            for (int rh = 0; rh < 2; ++rh) {
                int row = warp_m * 32 + i * 16 + (lane >> 2) + rh * 8;
                float v0 = fmaxf(c[i][jj][rh * 2 + 0] + b0, 0.f);
                float v1 = fmaxf(c[i][jj][rh * 2 + 1] + b1, 0.f);
                __nv_bfloat16 h0 = __float2bfloat16_rn(v0);
                __nv_bfloat16 h1 = __float2bfloat16_rn(v1);
                float l0 = v0 - __bfloat162float(h0);
                float l1 = v1 - __bfloat162float(h1);
                __nv_bfloat162 hp = __halves2bfloat162(h0, h1);
                __nv_bfloat162 lp = __halves2bfloat162(__float2bfloat16_rn(l0),
                                                       __float2bfloat16_rn(l1));
                *(__nv_bfloat162*)(smem + OFF_H + (ch * 2 + 0) * PLANE_A + (row * SP + kk) * 2) = hp;
                *(__nv_bfloat162*)(smem + OFF_H + (ch * 2 + 1) * PLANE_A + (row * SP + kk) * 2) = lp;
                c[i][jj][rh * 2 + 0] = 0.f;
                c[i][jj][rh * 2 + 1] = 0.f;
            }
        }
    }
}

__global__ void __launch_bounds__(128, 2) k_fused(
    const float* __restrict__ train, const float* __restrict__ agg,
    const __nv_bfloat16* __restrict__ wtb,
    const float* __restrict__ b1, const float* __restrict__ b2,
    const float* __restrict__ bc1, const float* __restrict__ bc2,
    float* __restrict__ outp)
{
    extern __shared__ __align__(16) char smem[];
    const int tid    = threadIdx.x;
    const int lane   = tid & 31;
    const int wid    = tid >> 5;
    const int warp_m = wid >> 1;     // 0..1 -> 32-row band
    const int warp_n = wid & 1;      // 0..1 -> 64-col band
    const int m0     = blockIdx.x * MT;

    const uint32_t afp_u = smem_u32(smem + OFF_AFP);
    const uint32_t bs_u  = smem_u32(smem + OFF_BS);
    float* Afp = (float*)(smem + OFF_AFP);

    float c[2][8][4];
    #pragma unroll
    for (int i = 0; i < 2; ++i)
        #pragma unroll
        for (int j = 0; j < 8; ++j)
            #pragma unroll
            for (int q = 0; q < 4; ++q) c[i][j][q] = 0.f;

    auto issue = [&](int cj, int stage) {
        Desc d = mkdesc(cj, train, agg, wtb);
        if (d.stream) {
            // A: 64 rows x 32 floats = 512 x 16B
            #pragma unroll
            for (int i = 0; i < 4; ++i) {
                int idx = i * 128 + tid;
                int row = idx >> 3, cc = idx & 7;
                int gr = m0 + row, k = d.k0 + cc * 4;
                int nb = 0;
                if (gr < NT) { int rem = d.K - k; nb = (rem >= 4) ? 16 : (rem > 0 ? rem * 4 : 0); }
                const float* src = nb ? (d.A + (size_t)gr * d.K + k) : d.A;
                CP16Z(afp_u + row * 144 + cc * 16, src, nb);
            }
        }
        CP_COMMIT();   // A group (possibly empty)
        #pragma unroll
        for (int p = 0; p < 2; ++p) {
            const __nv_bfloat16* bp = d.B + (size_t)p * 128 * 512;
            uint32_t bd = bs_u + (stage * 2 + p) * PLANE_B;
            #pragma unroll
            for (int i = 0; i < 4; ++i) {
                int idx = i * 128 + tid;
                int n = idx >> 2, cc = idx & 3;
                CP16(bd + n * 80 + cc * 16, bp + (size_t)n * 512 + d.bk0 + cc * 8);
            }
        }
        CP_COMMIT();   // B group
    };

    issue(0, 0);

    for (int j = 0; j < 36; ++j) {
        const int s = j & 1;
        Desc d = mkdesc(j, train, agg, wtb);

        CP_WAIT1();             // A(j) done
        __syncthreads();
        if (d.stream && tid < MT) {
            // convert fp32 staging -> bf16 hi/lo Astage[s]; one thread per row
            __nv_bfloat16* Ah = (__nv_bfloat16*)(smem + OFF_AST + (s * 2 + 0) * PLANE_A);
            __nv_bfloat16* Al = (__nv_bfloat16*)(smem + OFF_AST + (s * 2 + 1) * PLANE_A);
            const float* ar = Afp + tid * 36;
            uint32_t hp[16], lp[16];
            #pragma unroll
            for (int cc = 0; cc < 8; ++cc) {
                float4 f = *(const float4*)(ar + cc * 4);
                __nv_bfloat16 h0 = __float2bfloat16_rn(f.x);
                __nv_bfloat16 h1 = __float2bfloat16_rn(f.y);
                __nv_bfloat16 h2 = __float2bfloat16_rn(f.z);
                __nv_bfloat16 h3 = __float2bfloat16_rn(f.w);
                float l0 = f.x - __bfloat162float(h0);
                float l1 = f.y - __bfloat162float(h1);
                float l2 = f.z - __bfloat162float(h2);
                float l3 = f.w - __bfloat162float(h3);
                __nv_bfloat162 ph0 = __halves2bfloat162(h0, h1);
                __nv_bfloat162 ph1 = __halves2bfloat162(h2, h3);
                __nv_bfloat162 pl0 = __halves2bfloat162(__float2bfloat16_rn(l0), __float2bfloat16_rn(l1));
                __nv_bfloat162 pl1 = __halves2bfloat162(__float2bfloat16_rn(l2), __float2bfloat16_rn(l3));
                hp[cc * 2 + 0] = *(uint32_t*)&ph0;
                hp[cc * 2 + 1] = *(uint32_t*)&ph1;
                lp[cc * 2 + 0] = *(uint32_t*)&pl0;
                lp[cc * 2 + 1] = *(uint32_t*)&pl1;
            }
            uint32_t* dh = (uint32_t*)(Ah + tid * SP);
            uint32_t* dl = (uint32_t*)(Al + tid * SP);
            #pragma unroll
            for (int cc = 0; cc < 4; ++cc) {
                *(uint4*)(dh + cc * 4) = *(uint4*)(hp + cc * 4);
                *(uint4*)(dl + cc * 4) = *(uint4*)(lp + cc * 4);
            }
        }
        CP_WAIT0();             // B(j) done
        __syncthreads();

        if (j + 1 < 36) issue(j + 1, (j + 1) & 1);

        const char* Ab = d.stream ? (smem + OFF_AST + s * 2 * PLANE_A)
                                  : (smem + OFF_H + d.hch * 2 * PLANE_A);
        const char* Bb = smem + OFF_BS + s * 2 * PLANE_B;

        if (j < 32)           mma_chunk<8>(Ab, Bb, warp_m, warp_n, lane, c);
        else if (warp_n == 0) mma_chunk<2>(Ab, Bb, warp_m, warp_n, lane, c);

        if (j == 19)      epi_to_H(c, b1, smem, warp_m, warp_n, lane);
        else if (j == 27) epi_to_H(c, b2, smem, warp_m, warp_n, lane);
        else if (j == 31) epi_to_H(c, bc1, smem, warp_m, warp_n, lane);
    }

    // ---- cls store: out[NT,16] = c + bc2 (warp_n==0 warps hold cols 0..15) ----
    if (warp_n == 0) {
        #pragma unroll
        for (int i = 0; i < 2; ++i) {
            #pragma unroll
            for (int jj = 0; jj < 2; ++jj) {
                int col = jj * 8 + (lane & 3) * 2;
                float b0 = __ldg(&bc2[col]), b1 = __ldg(&bc2[col + 1]);
                #pragma unroll
                for (int rh = 0; rh < 2; ++rh) {
                    int row = m0 + warp_m * 32 + i * 16 + (lane >> 2) + rh * 8;
                    if (row < NT) {
                        float2 v = make_float2(c[i][jj][rh * 2 + 0] + b0,
                                               c[i][jj][rh * 2 + 1] + b1);
                        *(float2*)(outp + (size_t)row * NCLS + col) = v;
                    }
                }
            }
        }
    }
}

// ---------------- launch ----------------
extern "C" void kernel_launch(void* const* d_in, const int* in_sizes, int n_in,
                              void* d_out, int out_size)
{
    const float* gene  = (const float*)d_in[0];
    const float* train = (const float*)d_in[1];
    const int*   esrc  = (const int*)  d_in[2];
    const int*   edst  = (const int*)  d_in[3];
    const float* W1n   = (const float*)d_in[4];
    const float* W1s   = (const float*)d_in[5];
    const float* b1    = (const float*)d_in[6];
    const float* W2n   = (const float*)d_in[7];
    const float* W2s   = (const float*)d_in[8];
    const float* b2    = (const float*)d_in[9];
    const float* Wc1   = (const float*)d_in[10];
    const float* bc1   = (const float*)d_in[11];
    const float* Wc2   = (const float*)d_in[12];
    const float* bc2   = (const float*)d_in[13];
    float* out = (float*)d_out;

    float* agg;
    __nv_bfloat16* wtb;
    cudaGetSymbolAddress((void**)&agg, g_agg);
    cudaGetSymbolAddress((void**)&wtb, g_wtb);

    static bool attr_done = false;
    if (!attr_done) {
        cudaFuncSetAttribute(k_fused, cudaFuncAttributeMaxDynamicSharedMemorySize, SMEM_FUSED);
        attr_done = true;
    }

    k_trh<<<(6 * 65536 + 255) / 256, 256>>>(W1s, W1n, W2s, W2n, Wc1, Wc2, edst);
    k_scan<<<1, 1024>>>();
    k_scatter<<<(NE / 8 + 255) / 256, 256>>>(esrc, edst);
    k_spmm<<<(NT * 32 + 255) / 256, 256>>>(gene);
    k_fused<<<(NT + MT - 1) / MT, 128, SMEM_FUSED>>>(train, agg, wtb, b1, b2, bc1, bc2, out);

    (void)in_sizes; (void)n_in; (void)out_size;
}